// round 3
// baseline (speedup 1.0000x reference)
#include <cuda_runtime.h>
#include <math.h>

#define S_  512
#define L_  128
#define D_  256
#define H2_ 128
#define P_  16
#define B_  128
#define F_  256
#define FEAT_ 640
#define ED_ 64

// Pre-transposed weights (written by prologue kernel each launch — deterministic).
__device__ float g_attwT[D_ * H2_];     // [d][h]
__device__ float g_condT[FEAT_ * F_];   // [k][f]

__global__ __launch_bounds__(256) void transpose_kernel(
    const float* __restrict__ attw_W,   // [H2][D]
    const float* __restrict__ cond_W)   // [F][FEAT]
{
    int tid = blockIdx.x * blockDim.x + threadIdx.x;
    int stride = gridDim.x * blockDim.x;
    for (int i = tid; i < H2_ * D_; i += stride) {
        int h = i / D_, d = i % D_;
        g_attwT[d * H2_ + h] = attw_W[i];
    }
    for (int i = tid; i < F_ * FEAT_; i += stride) {
        int f = i / FEAT_, k = i % FEAT_;
        g_condT[k * F_ + f] = cond_W[i];
    }
}

__global__ __launch_bounds__(256) void fused_kernel(
    const int* __restrict__ x,        // [S, L]
    const int* __restrict__ ents,     // [B, 2]
    const int* __restrict__ spos,     // [B, P, 2]
    const int* __restrict__ tpos,     // [B, P, 2]
    const float* __restrict__ emb,    // [V, D]
    const float* __restrict__ ent_emb,// [E_V, ED]
    const float* __restrict__ attw_b, // [H2]
    const float* __restrict__ attw2_W,// [1, H2]
    const float* __restrict__ cond_b, // [F]
    const float* __restrict__ lin_W,  // [2, F]
    const float* __restrict__ lin_b,  // [2]
    float* __restrict__ out)          // [B, 2]
{
    const int b   = blockIdx.x;
    const int tid = threadIdx.x;
    const int wi  = tid >> 5;   // warp id 0..7  -> row group (4 rows each)
    const int lj  = tid & 31;   // lane          -> col group (4 cols each)

    __shared__ float Hm[32][D_ + 1];   // rows 0..15: s_h, 16..31: t_h (padded)
    __shared__ int   toks[32];
    __shared__ float logits[32];
    __shared__ float wgt[32];
    __shared__ float feats[FEAT_];
    __shared__ float r0s[8], r1s[8];

    // ---- token index lookup ----
    if (tid < 32) {
        int pool = tid >> 4, p = tid & 15;
        const int* pos = (pool == 0) ? spos : tpos;
        int s = pos[(b * P_ + p) * 2 + 0];
        int l = pos[(b * P_ + p) * 2 + 1];
        toks[tid] = x[s * L_ + l];
    }
    __syncthreads();

    // ---- gather embedding rows into shared ----
    #pragma unroll 4
    for (int r = 0; r < 32; r++) {
        Hm[r][tid] = emb[(size_t)toks[r] * D_ + tid];
    }
    __syncthreads();

    // ---- Phase B: E = H @ attwT  (32 x 128), 4x4 register tile / thread ----
    float acc00=0.f, acc01=0.f, acc02=0.f, acc03=0.f;
    float acc10=0.f, acc11=0.f, acc12=0.f, acc13=0.f;
    float acc20=0.f, acc21=0.f, acc22=0.f, acc23=0.f;
    float acc30=0.f, acc31=0.f, acc32=0.f, acc33=0.f;
    const float4* __restrict__ wT4 = reinterpret_cast<const float4*>(g_attwT) + lj;
    const int rbase = wi * 4;
    #pragma unroll 4
    for (int d = 0; d < D_; d++) {
        float4 w = wT4[d * (H2_ / 4)];
        float a0 = Hm[rbase + 0][d];
        float a1 = Hm[rbase + 1][d];
        float a2 = Hm[rbase + 2][d];
        float a3 = Hm[rbase + 3][d];
        acc00 += a0 * w.x; acc01 += a0 * w.y; acc02 += a0 * w.z; acc03 += a0 * w.w;
        acc10 += a1 * w.x; acc11 += a1 * w.y; acc12 += a1 * w.z; acc13 += a1 * w.w;
        acc20 += a2 * w.x; acc21 += a2 * w.y; acc22 += a2 * w.z; acc23 += a2 * w.w;
        acc30 += a3 * w.x; acc31 += a3 * w.y; acc32 += a3 * w.z; acc33 += a3 * w.w;
    }

    // tanh + attw2 weighting + reduce over h (cols)
    const int c0 = lj * 4;
    float bb0 = attw_b[c0+0], bb1 = attw_b[c0+1], bb2 = attw_b[c0+2], bb3 = attw_b[c0+3];
    float aw0 = attw2_W[c0+0], aw1 = attw2_W[c0+1], aw2 = attw2_W[c0+2], aw3 = attw2_W[c0+3];
    float part0 = tanhf(acc00+bb0)*aw0 + tanhf(acc01+bb1)*aw1 + tanhf(acc02+bb2)*aw2 + tanhf(acc03+bb3)*aw3;
    float part1 = tanhf(acc10+bb0)*aw0 + tanhf(acc11+bb1)*aw1 + tanhf(acc12+bb2)*aw2 + tanhf(acc13+bb3)*aw3;
    float part2 = tanhf(acc20+bb0)*aw0 + tanhf(acc21+bb1)*aw1 + tanhf(acc22+bb2)*aw2 + tanhf(acc23+bb3)*aw3;
    float part3 = tanhf(acc30+bb0)*aw0 + tanhf(acc31+bb1)*aw1 + tanhf(acc32+bb2)*aw2 + tanhf(acc33+bb3)*aw3;
    #pragma unroll
    for (int off = 16; off; off >>= 1) {
        part0 += __shfl_xor_sync(0xffffffffu, part0, off);
        part1 += __shfl_xor_sync(0xffffffffu, part1, off);
        part2 += __shfl_xor_sync(0xffffffffu, part2, off);
        part3 += __shfl_xor_sync(0xffffffffu, part3, off);
    }
    if (lj == 0) {
        logits[rbase + 0] = part0;
        logits[rbase + 1] = part1;
        logits[rbase + 2] = part2;
        logits[rbase + 3] = part3;
    }
    __syncthreads();

    // ---- softmax over P=16 per pool (threads 0 and 1) ----
    if (tid < 2) {
        int base = tid * 16;
        float mx = logits[base];
        #pragma unroll
        for (int p = 1; p < 16; p++) mx = fmaxf(mx, logits[base + p]);
        float e[16]; float sum = 0.f;
        #pragma unroll
        for (int p = 0; p < 16; p++) { e[p] = __expf(logits[base + p] - mx); sum += e[p]; }
        float inv = 1.f / sum;
        #pragma unroll
        for (int p = 0; p < 16; p++) wgt[base + p] = e[p] * inv;
    }
    __syncthreads();

    // ---- weighted pool + feature assembly ----
    {
        float sp = 0.f, tp = 0.f;
        #pragma unroll
        for (int p = 0; p < 16; p++) {
            sp += wgt[p]      * Hm[p][tid];
            tp += wgt[16 + p] * Hm[16 + p][tid];
        }
        feats[tid]      = sp;
        feats[D_ + tid] = tp;
    }
    if (tid < 128) {
        int which = tid >> 6;                 // 0 or 1
        int eidx  = ents[b * 2 + which];
        feats[2 * D_ + tid] = ent_emb[(size_t)eidx * ED_ + (tid & 63)];
    }
    __syncthreads();

    // ---- Phase C: condensed[f=tid] = feats . cond_W[f] + b; coalesced via g_condT ----
    const float* __restrict__ cT = g_condT + tid;
    float a0 = 0.f, a1 = 0.f, a2 = 0.f, a3 = 0.f;
    #pragma unroll 4
    for (int k = 0; k < FEAT_; k += 4) {
        a0 += feats[k+0] * cT[(k+0) * F_];
        a1 += feats[k+1] * cT[(k+1) * F_];
        a2 += feats[k+2] * cT[(k+2) * F_];
        a3 += feats[k+3] * cT[(k+3) * F_];
    }
    float th = tanhf(cond_b[tid] + ((a0 + a1) + (a2 + a3)));

    // ---- Phase D: score = tanh(condensed) @ lin_W^T + lin_b ----
    float p0 = th * lin_W[tid];
    float p1 = th * lin_W[F_ + tid];
    #pragma unroll
    for (int off = 16; off; off >>= 1) {
        p0 += __shfl_xor_sync(0xffffffffu, p0, off);
        p1 += __shfl_xor_sync(0xffffffffu, p1, off);
    }
    if (lj == 0) { r0s[wi] = p0; r1s[wi] = p1; }
    __syncthreads();
    if (tid == 0) {
        float s0 = lin_b[0], s1 = lin_b[1];
        #pragma unroll
        for (int w = 0; w < 8; w++) { s0 += r0s[w]; s1 += r1s[w]; }
        out[b * 2 + 0] = s0;
        out[b * 2 + 1] = s1;
    }
}

extern "C" void kernel_launch(void* const* d_in, const int* in_sizes, int n_in,
                              void* d_out, int out_size)
{
    const int*   x       = (const int*)  d_in[0];
    const int*   ents    = (const int*)  d_in[1];
    const int*   spos    = (const int*)  d_in[2];
    const int*   tpos    = (const int*)  d_in[3];
    const float* emb     = (const float*)d_in[4];
    const float* ent_emb = (const float*)d_in[5];
    const float* attw_W  = (const float*)d_in[6];
    const float* attw_b  = (const float*)d_in[7];
    const float* attw2_W = (const float*)d_in[8];
    const float* cond_W  = (const float*)d_in[9];
    const float* cond_b  = (const float*)d_in[10];
    const float* lin_W   = (const float*)d_in[11];
    const float* lin_b   = (const float*)d_in[12];
    float* out = (float*)d_out;

    transpose_kernel<<<148, 256>>>(attw_W, cond_W);
    fused_kernel<<<B_, 256>>>(x, ents, spos, tpos, emb, ent_emb,
                              attw_b, attw2_W, cond_b, lin_W, lin_b, out);
}

// round 4
// speedup vs baseline: 1.0635x; 1.0635x over previous
#include <cuda_runtime.h>
#include <math.h>

#define S_  512
#define L_  128
#define D_  256
#define H2_ 128
#define P_  16
#define B_  128
#define F_  256
#define FEAT_ 640
#define ED_ 64

typedef unsigned long long u64;

// Scratch (device globals — no allocations allowed)
__device__ float g_attwT[D_ * H2_];     // [d][h]
__device__ float g_condT[FEAT_ * F_];   // [k][f]
__device__ float g_featsT[FEAT_ * B_];  // [k][b]
__device__ float g_th[B_ * F_];         // [b][f]

__device__ __forceinline__ u64 pack2(float x, float y) {
    u64 r; asm("mov.b64 %0, {%1, %2};" : "=l"(r) : "f"(x), "f"(y)); return r;
}
__device__ __forceinline__ void unpack2(u64 v, float& x, float& y) {
    asm("mov.b64 {%0, %1}, %2;" : "=f"(x), "=f"(y) : "l"(v));
}
__device__ __forceinline__ void fma2(u64& d, u64 a, u64 b) {
    asm("fma.rn.f32x2 %0, %1, %2, %0;" : "+l"(d) : "l"(a), "l"(b));
}

__global__ __launch_bounds__(256) void transpose_kernel(
    const float* __restrict__ attw_W,   // [H2][D]
    const float* __restrict__ cond_W)   // [F][FEAT]
{
    int tid = blockIdx.x * blockDim.x + threadIdx.x;
    int stride = gridDim.x * blockDim.x;
    for (int i = tid; i < H2_ * D_; i += stride) {
        int h = i / D_, d = i % D_;
        g_attwT[d * H2_ + h] = attw_W[i];
    }
    for (int i = tid; i < F_ * FEAT_; i += stride) {
        int f = i / FEAT_, k = i % FEAT_;
        g_condT[k * F_ + f] = cond_W[i];
    }
}

// ---------------------------------------------------------------------------
// Pool kernel: gather + attn energies (f32x2 FMA, shared-staged attwT)
// grid = 128 (one CTA per b), 256 threads.
// Mapping phase B: lane = row (32 rows: 16 s + 16 t), warp = 16-col chunk.
// ---------------------------------------------------------------------------
__global__ __launch_bounds__(256) void pool_kernel(
    const int* __restrict__ x,        // [S, L]
    const int* __restrict__ ents,     // [B, 2]
    const int* __restrict__ spos,     // [B, P, 2]
    const int* __restrict__ tpos,     // [B, P, 2]
    const float* __restrict__ emb,    // [V, D]
    const float* __restrict__ ent_emb,// [E_V, ED]
    const float* __restrict__ attw_b, // [H2]
    const float* __restrict__ attw2_W)// [1, H2]
{
    const int b = blockIdx.x, tid = threadIdx.x;
    const int wi = tid >> 5, lane = tid & 31;

    extern __shared__ float sm[];
    float* Hm = sm;              // [32][257]
    float* ws = sm + 32 * 257;   // [2][64*128]

    __shared__ int   toks[32];
    __shared__ float part[8][33];
    __shared__ float logits[32];
    __shared__ float wgt[32];

    if (tid < 32) {
        int pool = tid >> 4, p = tid & 15;
        const int* pos = (pool == 0) ? spos : tpos;
        int s = pos[(b * P_ + p) * 2 + 0];
        int l = pos[(b * P_ + p) * 2 + 1];
        toks[tid] = x[s * L_ + l];
    }
    // stage attwT chunk 0 (d = 0..63) while toks settle
    {
        const float4* src = reinterpret_cast<const float4*>(g_attwT);
        float4* dst = reinterpret_cast<float4*>(ws);
        #pragma unroll
        for (int j = 0; j < 8; j++) dst[tid + 256 * j] = src[tid + 256 * j];
    }
    __syncthreads();

    // gather 32 embedding rows into shared (padded 257)
    #pragma unroll 4
    for (int r = 0; r < 32; r++)
        Hm[r * 257 + tid] = emb[(size_t)toks[r] * D_ + tid];
    __syncthreads();

    // ---- Phase B: E[row][col] over K=256, double-buffered 64-d chunks ----
    u64 acc[8];
    #pragma unroll
    for (int i = 0; i < 8; i++) acc[i] = 0ull;   // (0.0f, 0.0f)

    for (int c = 0; c < 4; c++) {
        int p = c & 1;
        if (c + 1 < 4) {  // prefetch next chunk into other buffer
            const float4* src = reinterpret_cast<const float4*>(g_attwT) + (c + 1) * 2048;
            float4* dst = reinterpret_cast<float4*>(ws + (1 - p) * 8192);
            #pragma unroll
            for (int j = 0; j < 8; j++) dst[tid + 256 * j] = src[tid + 256 * j];
        }
        const float* wb   = ws + p * 8192 + wi * 16;   // this warp's 16 cols
        const float* hrow = Hm + lane * 257 + c * 64;  // this lane's row, chunk d-range
        #pragma unroll 8
        for (int dd = 0; dd < 64; dd++) {
            float a = hrow[dd];
            u64 ap = pack2(a, a);
            const ulonglong2* wq = reinterpret_cast<const ulonglong2*>(wb + dd * 128);
            ulonglong2 q0 = wq[0], q1 = wq[1], q2 = wq[2], q3 = wq[3];
            fma2(acc[0], ap, q0.x); fma2(acc[1], ap, q0.y);
            fma2(acc[2], ap, q1.x); fma2(acc[3], ap, q1.y);
            fma2(acc[4], ap, q2.x); fma2(acc[5], ap, q2.y);
            fma2(acc[6], ap, q3.x); fma2(acc[7], ap, q3.y);
        }
        __syncthreads();
    }

    // tanh + attw2 weighting, partial sum over this warp's 16 cols
    {
        float colsum = 0.f;
        const int cbase = wi * 16;
        #pragma unroll
        for (int i = 0; i < 8; i++) {
            float e0, e1; unpack2(acc[i], e0, e1);
            int c = cbase + 2 * i;
            colsum += tanhf(e0 + attw_b[c])     * attw2_W[c];
            colsum += tanhf(e1 + attw_b[c + 1]) * attw2_W[c + 1];
        }
        part[wi][lane] = colsum;
    }
    __syncthreads();
    if (wi == 0) {
        float s = 0.f;
        #pragma unroll
        for (int w = 0; w < 8; w++) s += part[w][lane];
        logits[lane] = s;   // row = lane: 0..15 s-pool, 16..31 t-pool
    }
    __syncthreads();

    // softmax over P=16 per pool
    if (tid < 2) {
        int base = tid * 16;
        float mx = logits[base];
        #pragma unroll
        for (int p2 = 1; p2 < 16; p2++) mx = fmaxf(mx, logits[base + p2]);
        float e[16]; float sum = 0.f;
        #pragma unroll
        for (int p2 = 0; p2 < 16; p2++) { e[p2] = __expf(logits[base + p2] - mx); sum += e[p2]; }
        float inv = 1.f / sum;
        #pragma unroll
        for (int p2 = 0; p2 < 16; p2++) wgt[base + p2] = e[p2] * inv;
    }
    __syncthreads();

    // weighted pools + feature assembly -> transposed global feats [k][b]
    {
        float sp = 0.f, tp = 0.f;
        #pragma unroll
        for (int p2 = 0; p2 < 16; p2++) {
            sp += wgt[p2]      * Hm[p2 * 257 + tid];
            tp += wgt[16 + p2] * Hm[(16 + p2) * 257 + tid];
        }
        g_featsT[tid * B_ + b]        = sp;
        g_featsT[(D_ + tid) * B_ + b] = tp;
    }
    if (tid < 128) {
        int eidx = ents[b * 2 + (tid >> 6)];
        g_featsT[(2 * D_ + tid) * B_ + b] = ent_emb[(size_t)eidx * ED_ + (tid & 63)];
    }
}

// ---------------------------------------------------------------------------
// GEMM kernel: condensed = featsT^T @ condT, tanh, write g_th.
// grid = 64 (8 b-tiles x 8 f-tiles), 128 threads.
// warp -> 4 b rows, lane -> f column; K staged in 128-row double-buffered chunks.
// ---------------------------------------------------------------------------
__global__ __launch_bounds__(128) void gemm_kernel(const float* __restrict__ cond_b)
{
    const int tid = threadIdx.x, wi = tid >> 5, lane = tid & 31;
    const int bt = blockIdx.x >> 3, ft = blockIdx.x & 7;
    const int b0 = bt * 16, f0 = ft * 32;

    extern __shared__ float sm[];
    float* fT = sm;                 // [640][16]
    float* cs = sm + FEAT_ * 16;    // [2][128*32]

    // stage feats slice [640][16]
    for (int i = tid; i < FEAT_ * 16; i += 128) {
        int k = i >> 4, bb = i & 15;
        fT[i] = g_featsT[k * B_ + b0 + bb];
    }
    // stage cond chunk 0
    for (int r = wi; r < 128; r += 4)
        cs[r * 32 + lane] = g_condT[r * F_ + f0 + lane];
    __syncthreads();

    u64 acc01 = 0ull, acc23 = 0ull;
    for (int c = 0; c < 5; c++) {
        int p = c & 1;
        if (c + 1 < 5) {
            float* dst = cs + (1 - p) * 4096;
            const float* src = g_condT + (size_t)(c + 1) * 128 * F_ + f0;
            for (int r = wi; r < 128; r += 4)
                dst[r * 32 + lane] = src[r * F_ + lane];
        }
        const float* cb = cs + p * 4096;
        const float* fb = fT + c * 128 * 16 + wi * 4;
        #pragma unroll 8
        for (int kk = 0; kk < 128; kk++) {
            float w = cb[kk * 32 + lane];
            u64 wp = pack2(w, w);
            ulonglong2 aq = *reinterpret_cast<const ulonglong2*>(fb + kk * 16);
            fma2(acc01, wp, aq.x);
            fma2(acc23, wp, aq.y);
        }
        __syncthreads();
    }

    float a0, a1, a2, a3;
    unpack2(acc01, a0, a1); unpack2(acc23, a2, a3);
    float cbv = cond_b[f0 + lane];
    int bb = b0 + wi * 4;
    g_th[(bb + 0) * F_ + f0 + lane] = tanhf(a0 + cbv);
    g_th[(bb + 1) * F_ + f0 + lane] = tanhf(a1 + cbv);
    g_th[(bb + 2) * F_ + f0 + lane] = tanhf(a2 + cbv);
    g_th[(bb + 3) * F_ + f0 + lane] = tanhf(a3 + cbv);
}

// ---------------------------------------------------------------------------
// Head kernel: out[b][o] = g_th[b] . lin_W[o] + lin_b[o]
// ---------------------------------------------------------------------------
__global__ __launch_bounds__(64) void head_kernel(
    const float* __restrict__ lin_W, const float* __restrict__ lin_b,
    float* __restrict__ out)
{
    int b = blockIdx.x, o = threadIdx.x >> 5, lane = threadIdx.x & 31;
    float s = 0.f;
    #pragma unroll
    for (int f = lane; f < F_; f += 32)
        s += g_th[b * F_ + f] * lin_W[o * F_ + f];
    #pragma unroll
    for (int off = 16; off; off >>= 1) s += __shfl_xor_sync(0xffffffffu, s, off);
    if (lane == 0) out[b * 2 + o] = s + lin_b[o];
}

#define POOL_SMEM ((32 * 257 + 2 * 8192) * 4)   /* 98432 B */
#define GEMM_SMEM ((FEAT_ * 16 + 2 * 4096) * 4) /* 73728 B */

extern "C" void kernel_launch(void* const* d_in, const int* in_sizes, int n_in,
                              void* d_out, int out_size)
{
    const int*   x       = (const int*)  d_in[0];
    const int*   ents    = (const int*)  d_in[1];
    const int*   spos    = (const int*)  d_in[2];
    const int*   tpos    = (const int*)  d_in[3];
    const float* emb     = (const float*)d_in[4];
    const float* ent_emb = (const float*)d_in[5];
    const float* attw_W  = (const float*)d_in[6];
    const float* attw_b  = (const float*)d_in[7];
    const float* attw2_W = (const float*)d_in[8];
    const float* cond_W  = (const float*)d_in[9];
    const float* cond_b  = (const float*)d_in[10];
    const float* lin_W   = (const float*)d_in[11];
    const float* lin_b   = (const float*)d_in[12];
    float* out = (float*)d_out;

    cudaFuncSetAttribute(pool_kernel, cudaFuncAttributeMaxDynamicSharedMemorySize, POOL_SMEM);
    cudaFuncSetAttribute(gemm_kernel, cudaFuncAttributeMaxDynamicSharedMemorySize, GEMM_SMEM);

    transpose_kernel<<<148, 256>>>(attw_W, cond_W);
    pool_kernel<<<B_, 256, POOL_SMEM>>>(x, ents, spos, tpos, emb, ent_emb, attw_b, attw2_W);
    gemm_kernel<<<64, 128, GEMM_SMEM>>>(cond_b);
    head_kernel<<<B_, 64>>>(lin_W, lin_b, out);
}

// round 5
// speedup vs baseline: 1.5560x; 1.4631x over previous
#include <cuda_runtime.h>
#include <math.h>

#define S_  512
#define L_  128
#define D_  256
#define H2_ 128
#define P_  16
#define B_  128
#define F_  256
#define FEAT_ 640
#define ED_ 64

typedef unsigned long long u64;

// Scratch (device globals — no allocations allowed)
__device__ float g_featsT[FEAT_ * B_];  // [k][b]
__device__ float g_th[B_ * F_];         // [b][f]

__device__ __forceinline__ u64 pack2(float x, float y) {
    u64 r; asm("mov.b64 %0, {%1, %2};" : "=l"(r) : "f"(x), "f"(y)); return r;
}
__device__ __forceinline__ void unpack2(u64 v, float& x, float& y) {
    asm("mov.b64 {%0, %1}, %2;" : "=f"(x), "=f"(y) : "l"(v));
}
__device__ __forceinline__ void fma2(u64& d, u64 a, u64 b) {
    asm("fma.rn.f32x2 %0, %1, %2, %0;" : "+l"(d) : "l"(a), "l"(b));
}

// ---------------------------------------------------------------------------
// Pool kernel. grid = (128 b, 2 pool), 256 threads. CTA handles 16 rows.
// Phase B mapping: warp wi -> 16 cols, ch=lane>>4 -> col-oct, row=lane&15.
// attw_W is transposed into smem during staging (no separate kernel).
// ---------------------------------------------------------------------------
#define WS_PITCH 132                    /* floats per d-row (128 + 4 pad), /4 ok */
#define WS_CHUNK (64 * WS_PITCH)        /* one 64-d chunk */
#define HM_PITCH 257

__global__ __launch_bounds__(256) void pool_kernel(
    const int* __restrict__ x,        // [S, L]
    const int* __restrict__ ents,     // [B, 2]
    const int* __restrict__ spos,     // [B, P, 2]
    const int* __restrict__ tpos,     // [B, P, 2]
    const float* __restrict__ emb,    // [V, D]
    const float* __restrict__ ent_emb,// [E_V, ED]
    const float* __restrict__ attw_W, // [H2, D]
    const float* __restrict__ attw_b, // [H2]
    const float* __restrict__ attw2_W)// [1, H2]
{
    const int b = blockIdx.x, pool = blockIdx.y, tid = threadIdx.x;
    const int wi = tid >> 5, lane = tid & 31;
    const int ch = lane >> 4, row = lane & 15;
    const int col0 = wi * 16 + ch * 8;

    extern __shared__ float sm[];
    float* Hm = sm;                      // [16][257]
    float* ws = sm + 16 * HM_PITCH;      // [2][WS_CHUNK] : wT[d][h]

    __shared__ int   toks[16];
    __shared__ float part[16][17];
    __shared__ float logits[16];
    __shared__ float wgt[16];

    const int* pos = (pool == 0) ? spos : tpos;
    if (tid < 16) {
        int s = pos[(b * P_ + tid) * 2 + 0];
        int l = pos[(b * P_ + tid) * 2 + 1];
        toks[tid] = x[s * L_ + l];
    }

    // stage attwT chunk 0 (d in [0,64)) transposed: ws[d][h] = attw_W[h][d]
    {
        const float4* src = reinterpret_cast<const float4*>(attw_W);
        #pragma unroll
        for (int j = 0; j < 8; j++) {
            int i = tid + 256 * j;            // 2048 float4 items
            int d4 = i >> 7, h = i & 127;     // lane-consecutive h -> conflict-free STS
            float4 v = src[h * 64 + d4];
            ws[(4 * d4 + 0) * WS_PITCH + h] = v.x;
            ws[(4 * d4 + 1) * WS_PITCH + h] = v.y;
            ws[(4 * d4 + 2) * WS_PITCH + h] = v.z;
            ws[(4 * d4 + 3) * WS_PITCH + h] = v.w;
        }
    }
    __syncthreads();

    // gather 16 embedding rows
    #pragma unroll 4
    for (int r = 0; r < 16; r++)
        Hm[r * HM_PITCH + tid] = emb[(size_t)toks[r] * D_ + tid];
    __syncthreads();

    // ---- Phase B: E[row][col] over K=256, double-buffered 64-d chunks ----
    u64 acc0 = 0ull, acc1 = 0ull, acc2 = 0ull, acc3 = 0ull;  // 8 cols
    for (int c = 0; c < 4; c++) {
        int p = c & 1;
        if (c + 1 < 4) {
            const float4* src = reinterpret_cast<const float4*>(attw_W) + (c + 1) * 16;
            float* dst = ws + (1 - p) * WS_CHUNK;
            #pragma unroll
            for (int j = 0; j < 8; j++) {
                int i = tid + 256 * j;
                int d4 = i >> 7, h = i & 127;
                float4 v = src[h * 64 + d4];
                dst[(4 * d4 + 0) * WS_PITCH + h] = v.x;
                dst[(4 * d4 + 1) * WS_PITCH + h] = v.y;
                dst[(4 * d4 + 2) * WS_PITCH + h] = v.z;
                dst[(4 * d4 + 3) * WS_PITCH + h] = v.w;
            }
        }
        const float* wb   = ws + p * WS_CHUNK + col0;
        const float* hrow = Hm + row * HM_PITCH + c * 64;
        #pragma unroll 8
        for (int dd = 0; dd < 64; dd++) {
            float a = hrow[dd];
            u64 ap = pack2(a, a);
            const ulonglong2* wq = reinterpret_cast<const ulonglong2*>(wb + dd * WS_PITCH);
            ulonglong2 q0 = wq[0], q1 = wq[1];
            fma2(acc0, ap, q0.x); fma2(acc1, ap, q0.y);
            fma2(acc2, ap, q1.x); fma2(acc3, ap, q1.y);
        }
        __syncthreads();
    }

    // tanh + attw2 weighting, partial over this thread's 8 cols
    {
        float colsum = 0.f;
        float e0, e1;
        unpack2(acc0, e0, e1);
        colsum += tanhf(e0 + attw_b[col0+0]) * attw2_W[col0+0];
        colsum += tanhf(e1 + attw_b[col0+1]) * attw2_W[col0+1];
        unpack2(acc1, e0, e1);
        colsum += tanhf(e0 + attw_b[col0+2]) * attw2_W[col0+2];
        colsum += tanhf(e1 + attw_b[col0+3]) * attw2_W[col0+3];
        unpack2(acc2, e0, e1);
        colsum += tanhf(e0 + attw_b[col0+4]) * attw2_W[col0+4];
        colsum += tanhf(e1 + attw_b[col0+5]) * attw2_W[col0+5];
        unpack2(acc3, e0, e1);
        colsum += tanhf(e0 + attw_b[col0+6]) * attw2_W[col0+6];
        colsum += tanhf(e1 + attw_b[col0+7]) * attw2_W[col0+7];
        part[wi * 2 + ch][row] = colsum;
    }
    __syncthreads();
    if (tid < 16) {
        float s = 0.f;
        #pragma unroll
        for (int q = 0; q < 16; q++) s += part[q][tid];
        logits[tid] = s;
    }
    __syncthreads();

    // softmax over P=16
    if (tid == 0) {
        float mx = logits[0];
        #pragma unroll
        for (int p2 = 1; p2 < 16; p2++) mx = fmaxf(mx, logits[p2]);
        float e[16]; float sum = 0.f;
        #pragma unroll
        for (int p2 = 0; p2 < 16; p2++) { e[p2] = __expf(logits[p2] - mx); sum += e[p2]; }
        float inv = 1.f / sum;
        #pragma unroll
        for (int p2 = 0; p2 < 16; p2++) wgt[p2] = e[p2] * inv;
    }
    __syncthreads();

    // weighted pool -> g_featsT[k][b] (s-pool: k=0..255, t-pool: k=256..511)
    {
        float sp = 0.f;
        #pragma unroll
        for (int p2 = 0; p2 < 16; p2++)
            sp += wgt[p2] * Hm[p2 * HM_PITCH + tid];
        g_featsT[(pool * D_ + tid) * B_ + b] = sp;
    }
    if (pool == 0 && tid < 128) {
        int eidx = ents[b * 2 + (tid >> 6)];
        g_featsT[(2 * D_ + tid) * B_ + b] = ent_emb[(size_t)eidx * ED_ + (tid & 63)];
    }
}

// ---------------------------------------------------------------------------
// GEMM: condensed = feats @ cond_W^T, tanh -> g_th.
// grid = 128 (16 b-tiles x 8 f-tiles), 128 threads. Tile 8b x 32f.
// lane -> f, warp -> b-pair (packed u64 acc). cond_W transposed in-smem.
// ---------------------------------------------------------------------------
#define CS_PITCH 33
#define CS_CHUNK (128 * CS_PITCH)

__global__ __launch_bounds__(128) void gemm_kernel(
    const float* __restrict__ cond_W,   // [F][FEAT]
    const float* __restrict__ cond_b)
{
    const int tid = threadIdx.x, wi = tid >> 5, lane = tid & 31;
    const int bt = blockIdx.x >> 3, ft = blockIdx.x & 7;
    const int b0 = bt * 8, f0 = ft * 32;

    extern __shared__ float sm[];
    float* fs = sm;                      // [640][8]  feats slice
    float* cs = sm + FEAT_ * 8;          // [2][128][33]  condT chunk

    // stage feats slice [640][8]
    #pragma unroll
    for (int j = 0; j < 40; j++) {
        int i = tid + 128 * j;           // i = k*8 + bb
        fs[i] = g_featsT[(i >> 3) * B_ + b0 + (i & 7)];
    }
    // stage cond chunk 0: cs[k][f] = cond_W[f0+f][k], k in [0,128)
    {
        const float4* src = reinterpret_cast<const float4*>(cond_W);
        #pragma unroll
        for (int j = 0; j < 8; j++) {
            int i = tid + 128 * j;        // 1024 float4 items
            int k4 = i >> 5, f = i & 31;  // lane-consecutive f -> conflict-free STS
            float4 v = src[(f0 + f) * 160 + k4];
            cs[(4 * k4 + 0) * CS_PITCH + f] = v.x;
            cs[(4 * k4 + 1) * CS_PITCH + f] = v.y;
            cs[(4 * k4 + 2) * CS_PITCH + f] = v.z;
            cs[(4 * k4 + 3) * CS_PITCH + f] = v.w;
        }
    }
    __syncthreads();

    u64 acc = 0ull;   // (b0+wi*2, b0+wi*2+1)
    for (int c = 0; c < 5; c++) {
        int p = c & 1;
        if (c + 1 < 5) {
            const float4* src = reinterpret_cast<const float4*>(cond_W) + (c + 1) * 32;
            float* dst = cs + (1 - p) * CS_CHUNK;
            #pragma unroll
            for (int j = 0; j < 8; j++) {
                int i = tid + 128 * j;
                int k4 = i >> 5, f = i & 31;
                float4 v = src[(f0 + f) * 160 + k4];
                dst[(4 * k4 + 0) * CS_PITCH + f] = v.x;
                dst[(4 * k4 + 1) * CS_PITCH + f] = v.y;
                dst[(4 * k4 + 2) * CS_PITCH + f] = v.z;
                dst[(4 * k4 + 3) * CS_PITCH + f] = v.w;
            }
        }
        const float* cb = cs + p * CS_CHUNK + lane;
        const float* fb = fs + c * 128 * 8 + wi * 2;
        #pragma unroll 8
        for (int kk = 0; kk < 128; kk++) {
            float w = cb[kk * CS_PITCH];
            u64 ap = *reinterpret_cast<const u64*>(fb + kk * 8);
            fma2(acc, pack2(w, w), ap);
        }
        __syncthreads();
    }

    float a0, a1; unpack2(acc, a0, a1);
    float cbv = cond_b[f0 + lane];
    int bb = b0 + wi * 2;
    g_th[(bb + 0) * F_ + f0 + lane] = tanhf(a0 + cbv);
    g_th[(bb + 1) * F_ + f0 + lane] = tanhf(a1 + cbv);
}

// ---------------------------------------------------------------------------
// Head: out[b][o] = g_th[b] . lin_W[o] + lin_b[o]
// ---------------------------------------------------------------------------
__global__ __launch_bounds__(64) void head_kernel(
    const float* __restrict__ lin_W, const float* __restrict__ lin_b,
    float* __restrict__ out)
{
    int b = blockIdx.x, o = threadIdx.x >> 5, lane = threadIdx.x & 31;
    float s = 0.f;
    #pragma unroll
    for (int f = lane; f < F_; f += 32)
        s += g_th[b * F_ + f] * lin_W[o * F_ + f];
    #pragma unroll
    for (int off = 16; off; off >>= 1) s += __shfl_xor_sync(0xffffffffu, s, off);
    if (lane == 0) out[b * 2 + o] = s + lin_b[o];
}

#define POOL_SMEM ((16 * HM_PITCH + 2 * WS_CHUNK) * 4)   /* 83,984 B */
#define GEMM_SMEM ((FEAT_ * 8 + 2 * CS_CHUNK) * 4)       /* 54,272 B */

extern "C" void kernel_launch(void* const* d_in, const int* in_sizes, int n_in,
                              void* d_out, int out_size)
{
    const int*   x       = (const int*)  d_in[0];
    const int*   ents    = (const int*)  d_in[1];
    const int*   spos    = (const int*)  d_in[2];
    const int*   tpos    = (const int*)  d_in[3];
    const float* emb     = (const float*)d_in[4];
    const float* ent_emb = (const float*)d_in[5];
    const float* attw_W  = (const float*)d_in[6];
    const float* attw_b  = (const float*)d_in[7];
    const float* attw2_W = (const float*)d_in[8];
    const float* cond_W  = (const float*)d_in[9];
    const float* cond_b  = (const float*)d_in[10];
    const float* lin_W   = (const float*)d_in[11];
    const float* lin_b   = (const float*)d_in[12];
    float* out = (float*)d_out;

    cudaFuncSetAttribute(pool_kernel, cudaFuncAttributeMaxDynamicSharedMemorySize, POOL_SMEM);
    cudaFuncSetAttribute(gemm_kernel, cudaFuncAttributeMaxDynamicSharedMemorySize, GEMM_SMEM);

    dim3 pgrid(B_, 2);
    pool_kernel<<<pgrid, 256, POOL_SMEM>>>(x, ents, spos, tpos, emb, ent_emb,
                                           attw_W, attw_b, attw2_W);
    gemm_kernel<<<128, 128, GEMM_SMEM>>>(cond_W, cond_b);
    head_kernel<<<B_, 64>>>(lin_W, lin_b, out);
}

// round 7
// speedup vs baseline: 2.0711x; 1.3311x over previous
#include <cuda_runtime.h>
#include <math.h>

#define S_  512
#define L_  128
#define D_  256
#define H2_ 128
#define P_  16
#define B_  128
#define F_  256
#define FEAT_ 640
#define ED_ 64
#define GRID_ 148
#define NT_ 256

typedef unsigned long long u64;

// Scratch (device globals — no allocations allowed)
__device__ float g_attwT[D_ * H2_];     // [d][h]
__device__ float g_condT[FEAT_ * F_];   // [k][f]
__device__ float g_featsT[FEAT_ * B_];  // [k][b]
__device__ float g_th[B_ * F_];         // [b][f]
__device__ unsigned g_bar;              // zero-init; monotonic across replays

__device__ __forceinline__ u64 pack2(float x, float y) {
    u64 r; asm("mov.b64 %0, {%1, %2};" : "=l"(r) : "f"(x), "f"(y)); return r;
}
__device__ __forceinline__ void unpack2(u64 v, float& x, float& y) {
    asm("mov.b64 {%0, %1}, %2;" : "=f"(x), "=f"(y) : "l"(v));
}
__device__ __forceinline__ void fma2(u64& d, u64 a, u64 b) {
    asm("fma.rn.f32x2 %0, %1, %2, %0;" : "+l"(d) : "l"(a), "l"(b));
}

__device__ __forceinline__ void grid_sync() {
    __syncthreads();
    if (threadIdx.x == 0) {
        __threadfence();
        unsigned ticket = atomicAdd(&g_bar, 1u);
        unsigned target = (ticket / GRID_ + 1u) * GRID_;
        volatile unsigned* p = &g_bar;
        while (*p < target) { }
        __threadfence();
    }
    __syncthreads();
}

__global__ __launch_bounds__(NT_, 1) void fused_all(
    const int* __restrict__ x,        // [S, L]
    const int* __restrict__ ents,     // [B, 2]
    const int* __restrict__ spos,     // [B, P, 2]
    const int* __restrict__ tpos,     // [B, P, 2]
    const float* __restrict__ emb,    // [V, D]
    const float* __restrict__ ent_emb,// [E_V, ED]
    const float* __restrict__ attw_W, // [H2, D]
    const float* __restrict__ attw_b, // [H2]
    const float* __restrict__ attw2_W,// [1, H2]
    const float* __restrict__ cond_W, // [F, FEAT]
    const float* __restrict__ cond_b, // [F]
    const float* __restrict__ lin_W,  // [2, F]
    const float* __restrict__ lin_b,  // [2]
    float* __restrict__ out)          // [B, 2]
{
    extern __shared__ float sm[];
    const int cta = blockIdx.x, tid = threadIdx.x;
    const int wi = tid >> 5, lane = tid & 31;

    __shared__ int   toks[32];
    __shared__ float parts[16][18];
    __shared__ float partt[16][18];
    __shared__ float logits[32];
    __shared__ float wgt[32];
    __shared__ u64   sp2[8][32];
    __shared__ float r0s[8], r1s[8];

    // ================= Phase 0: transposes (coalesced reads) =================
    {
        int gt = cta * NT_ + tid, gs = GRID_ * NT_;
        for (int i = gt; i < H2_ * D_; i += gs) {       // i = h*256 + d
            int h = i >> 8, d = i & 255;
            g_attwT[d * H2_ + h] = attw_W[i];
        }
        for (int i = gt; i < F_ * FEAT_; i += gs) {     // i = f*640 + k
            int f = i / FEAT_;
            int k = i - f * FEAT_;
            g_condT[k * F_ + f] = cond_W[i];
        }
    }
    grid_sync();

    // ================= Phase 1: pool (one b per CTA, both pools) =============
    {
        // stage full attwT [d][h] as straight coalesced copy (128 KB)
        const float4* src = reinterpret_cast<const float4*>(g_attwT);
        float4* dst = reinterpret_cast<float4*>(sm);
        #pragma unroll
        for (int j = 0; j < 32; j++) dst[tid + NT_ * j] = src[tid + NT_ * j];
    }
    float* ws  = sm;                 // [256][128]
    float* Hm2 = sm + D_ * H2_;      // [16][257*2] rows pair-packed (s,t)

    const int b = cta;
    if (b < B_) {
        if (tid < 32) {
            int pool = tid >> 4, p = tid & 15;
            const int* pos = pool ? tpos : spos;
            int s = pos[(b * P_ + p) * 2 + 0];
            int l = pos[(b * P_ + p) * 2 + 1];
            toks[tid] = x[s * L_ + l];
        }
        __syncthreads();
        #pragma unroll 4
        for (int r = 0; r < 32; r++) {
            float v = emb[(size_t)toks[r] * D_ + tid];
            Hm2[(r & 15) * 514 + tid * 2 + (r >> 4)] = v;
        }
        __syncthreads();

        const int ch = lane >> 4, rr = lane & 15;
        const int col0 = wi * 16 + ch * 8;
        const float* wrow = ws + col0;
        const float* hrow = Hm2 + rr * 514;
        u64 aA0=0,aA1=0,aA2=0,aA3=0, aB0=0,aB1=0,aB2=0,aB3=0;
        #pragma unroll 4
        for (int d = 0; d < D_; d++) {
            u64 hp = *reinterpret_cast<const u64*>(hrow + 2 * d);
            float a0, a1; unpack2(hp, a0, a1);
            u64 p0 = pack2(a0, a0), p1 = pack2(a1, a1);
            const ulonglong2* wq = reinterpret_cast<const ulonglong2*>(wrow + d * H2_);
            ulonglong2 q0 = wq[0], q1 = wq[1];
            fma2(aA0, p0, q0.x); fma2(aA1, p0, q0.y);
            fma2(aA2, p0, q1.x); fma2(aA3, p0, q1.y);
            fma2(aB0, p1, q0.x); fma2(aB1, p1, q0.y);
            fma2(aB2, p1, q1.x); fma2(aB3, p1, q1.y);
        }

        float cs_ = 0.f, ct_ = 0.f;
        {
            float e0, e1;
            unpack2(aA0,e0,e1); cs_ += tanhf(e0+attw_b[col0+0])*attw2_W[col0+0] + tanhf(e1+attw_b[col0+1])*attw2_W[col0+1];
            unpack2(aA1,e0,e1); cs_ += tanhf(e0+attw_b[col0+2])*attw2_W[col0+2] + tanhf(e1+attw_b[col0+3])*attw2_W[col0+3];
            unpack2(aA2,e0,e1); cs_ += tanhf(e0+attw_b[col0+4])*attw2_W[col0+4] + tanhf(e1+attw_b[col0+5])*attw2_W[col0+5];
            unpack2(aA3,e0,e1); cs_ += tanhf(e0+attw_b[col0+6])*attw2_W[col0+6] + tanhf(e1+attw_b[col0+7])*attw2_W[col0+7];
            unpack2(aB0,e0,e1); ct_ += tanhf(e0+attw_b[col0+0])*attw2_W[col0+0] + tanhf(e1+attw_b[col0+1])*attw2_W[col0+1];
            unpack2(aB1,e0,e1); ct_ += tanhf(e0+attw_b[col0+2])*attw2_W[col0+2] + tanhf(e1+attw_b[col0+3])*attw2_W[col0+3];
            unpack2(aB2,e0,e1); ct_ += tanhf(e0+attw_b[col0+4])*attw2_W[col0+4] + tanhf(e1+attw_b[col0+5])*attw2_W[col0+5];
            unpack2(aB3,e0,e1); ct_ += tanhf(e0+attw_b[col0+6])*attw2_W[col0+6] + tanhf(e1+attw_b[col0+7])*attw2_W[col0+7];
        }
        parts[rr][wi * 2 + ch] = cs_;
        partt[rr][wi * 2 + ch] = ct_;
        __syncthreads();
        if (tid < 32) {
            int pool = tid >> 4, r = tid & 15;
            const float* pt = pool ? &partt[r][0] : &parts[r][0];
            float s = 0.f;
            #pragma unroll
            for (int q = 0; q < 16; q++) s += pt[q];
            logits[tid] = s;
        }
        __syncthreads();
        if (tid < 2) {
            int base = tid * 16;
            float mx = logits[base];
            #pragma unroll
            for (int p2 = 1; p2 < 16; p2++) mx = fmaxf(mx, logits[base + p2]);
            float e[16]; float sum = 0.f;
            #pragma unroll
            for (int p2 = 0; p2 < 16; p2++) { e[p2] = __expf(logits[base + p2] - mx); sum += e[p2]; }
            float inv = 1.f / sum;
            #pragma unroll
            for (int p2 = 0; p2 < 16; p2++) wgt[base + p2] = e[p2] * inv;
        }
        __syncthreads();
        {
            float sp = 0.f, tp = 0.f;
            #pragma unroll
            for (int p2 = 0; p2 < 16; p2++) {
                sp += wgt[p2]      * Hm2[p2 * 514 + tid * 2 + 0];
                tp += wgt[16 + p2] * Hm2[p2 * 514 + tid * 2 + 1];
            }
            g_featsT[tid * B_ + b]        = sp;
            g_featsT[(D_ + tid) * B_ + b] = tp;
        }
        if (tid < 128) {
            int eidx = ents[b * 2 + (tid >> 6)];
            g_featsT[(2 * D_ + tid) * B_ + b] = ent_emb[(size_t)eidx * ED_ + (tid & 63)];
        }
    }
    grid_sync();

    // ================= Phase 2: gemm (128 tile-tasks, 8b x 32f) ==============
    if (cta < 128) {
        const int bt = cta >> 3, ft = cta & 7;
        const int b0 = bt * 8, f0 = ft * 32;
        float* fs  = sm;                 // [640][8]
        float* cst = sm + FEAT_ * 8;     // [640][33]

        #pragma unroll
        for (int j = 0; j < 20; j++) {
            int i = tid + NT_ * j;       // 5120 items: k=i>>3, bb=i&7 (coalesced read)
            fs[i] = g_featsT[(i >> 3) * B_ + b0 + (i & 7)];
        }
        #pragma unroll
        for (int j = 0; j < 80; j++) {   // 20480 items (coalesced read)
            int i = tid + NT_ * j;
            int k = i >> 5, f = i & 31;
            cst[k * 33 + f] = g_condT[k * F_ + f0 + f];
        }
        __syncthreads();

        const int pr = wi & 3, kh = wi >> 2;   // b-pair, k-half
        const float* cb = cst + kh * 320 * 33 + lane;
        const float* fb = fs + kh * 320 * 8 + pr * 2;
        u64 acc = 0ull;
        #pragma unroll 8
        for (int kk = 0; kk < 320; kk++) {
            float w = cb[kk * 33];
            u64 fp = *reinterpret_cast<const u64*>(fb + kk * 8);
            fma2(acc, pack2(w, w), fp);
        }
        sp2[wi][lane] = acc;
        __syncthreads();
        if (wi < 4) {
            float x0, x1, y0, y1;
            unpack2(sp2[wi][lane], x0, x1);
            unpack2(sp2[wi + 4][lane], y0, y1);
            float cbv = cond_b[f0 + lane];
            int bb = b0 + wi * 2;
            g_th[(bb + 0) * F_ + f0 + lane] = tanhf(x0 + y0 + cbv);
            g_th[(bb + 1) * F_ + f0 + lane] = tanhf(x1 + y1 + cbv);
        }
    }
    grid_sync();

    // ================= Phase 3: head ========================================
    if (cta < B_) {
        float t  = g_th[cta * F_ + tid];
        float q0 = t * lin_W[tid];
        float q1 = t * lin_W[F_ + tid];
        #pragma unroll
        for (int off = 16; off; off >>= 1) {
            q0 += __shfl_xor_sync(0xffffffffu, q0, off);
            q1 += __shfl_xor_sync(0xffffffffu, q1, off);
        }
        if (lane == 0) { r0s[wi] = q0; r1s[wi] = q1; }
        __syncthreads();
        if (tid == 0) {
            float s0 = lin_b[0], s1 = lin_b[1];
            #pragma unroll
            for (int w = 0; w < 8; w++) { s0 += r0s[w]; s1 += r1s[w]; }
            out[cta * 2 + 0] = s0;
            out[cta * 2 + 1] = s1;
        }
    }
}

#define DYN_SMEM ((D_ * H2_ + 16 * 514) * 4)   /* 163,968 B (phase 1 is max) */

extern "C" void kernel_launch(void* const* d_in, const int* in_sizes, int n_in,
                              void* d_out, int out_size)
{
    const int*   x       = (const int*)  d_in[0];
    const int*   ents    = (const int*)  d_in[1];
    const int*   spos    = (const int*)  d_in[2];
    const int*   tpos    = (const int*)  d_in[3];
    const float* emb     = (const float*)d_in[4];
    const float* ent_emb = (const float*)d_in[5];
    const float* attw_W  = (const float*)d_in[6];
    const float* attw_b  = (const float*)d_in[7];
    const float* attw2_W = (const float*)d_in[8];
    const float* cond_W  = (const float*)d_in[9];
    const float* cond_b  = (const float*)d_in[10];
    const float* lin_W   = (const float*)d_in[11];
    const float* lin_b   = (const float*)d_in[12];
    float* out = (float*)d_out;

    cudaFuncSetAttribute(fused_all, cudaFuncAttributeMaxDynamicSharedMemorySize, DYN_SMEM);
    fused_all<<<GRID_, NT_, DYN_SMEM>>>(x, ents, spos, tpos, emb, ent_emb,
                                        attw_W, attw_b, attw2_W,
                                        cond_W, cond_b, lin_W, lin_b, out);
}